// round 4
// baseline (speedup 1.0000x reference)
#include <cuda_runtime.h>
#include <cuda_fp16.h>

#define TT  30
#define TD  150
#define DIM 512
#define NEGF (-1e30f)
#define MAX_ROWS 34836   // WORDS_CNT + 1

// fp16 copy of the embedding table (zero-init .bss, no allocation)
__device__ __half g_w2v_h[(size_t)MAX_ROWS * DIM];

// ---- pass 1: fp32 -> fp16 table conversion ---------------------------------
__global__ __launch_bounds__(256)
void w2v_convert_kernel(const float4* __restrict__ src, uint2* __restrict__ dst, int n4)
{
    int i      = blockIdx.x * 256 + threadIdx.x;
    int stride = gridDim.x * 256;
    for (; i < n4; i += stride) {
        const float4 f = __ldcs(&src[i]);           // streaming: don't pollute L2
        __half2 a = __floats2half2_rn(f.x, f.y);
        __half2 b = __floats2half2_rn(f.z, f.w);
        uint2 u;
        u.x = *reinterpret_cast<const unsigned*>(&a);
        u.y = *reinterpret_cast<const unsigned*>(&b);
        dst[i] = u;                                  // normal store: keep fp16 in L2
    }
}

// ---- pass 2: gather + pool --------------------------------------------------
__global__ __launch_bounds__(128, 8)
void swem_cat_kernel(const void* __restrict__ title_v,
                     const void* __restrict__ desc_v,
                     const void* __restrict__ tlen_v,
                     const void* __restrict__ dlen_v,
                     float* __restrict__ out)
{
    __shared__ int s_idx[TT + TD];
    __shared__ int s_len[2];
    __shared__ int s_is64;

    const int b   = blockIdx.x;
    const int tid = threadIdx.x;

    // dtype detection: int64 vs int32 indices (values < 34836 => high word 0)
    if (tid < 32) {
        unsigned hi  = ((const unsigned*)title_v)[2 * tid + 1];
        unsigned any = __ballot_sync(0xffffffffu, hi != 0u);
        if (tid == 0) s_is64 = (any == 0u) ? 1 : 0;
    }
    __syncthreads();

    if (s_is64) {
        const long long* tp = (const long long*)title_v + (long long)b * TT;
        const long long* dp = (const long long*)desc_v  + (long long)b * TD;
        if (tid < TT) s_idx[tid] = (int)tp[tid];
        for (int i = tid; i < TD; i += 128) s_idx[TT + i] = (int)dp[i];
        if (tid == 0) {
            s_len[0] = (int)((const long long*)tlen_v)[b];
            s_len[1] = (int)((const long long*)dlen_v)[b];
        }
    } else {
        const int* tp = (const int*)title_v + b * TT;
        const int* dp = (const int*)desc_v  + b * TD;
        if (tid < TT) s_idx[tid] = tp[tid];
        for (int i = tid; i < TD; i += 128) s_idx[TT + i] = dp[i];
        if (tid == 0) {
            s_len[0] = ((const int*)tlen_v)[b];
            s_len[1] = ((const int*)dlen_v)[b];
        }
    }
    __syncthreads();

    const int tl = s_len[0];
    const int dl = s_len[1];
    const __half* hbase = g_w2v_h + tid * 4;          // per-thread 4-dim slice
    float* orow = out + (size_t)b * (4 * DIM) + tid * 4;

    // ---- title pool ---------------------------------------------------------
    {
        float4 mx = make_float4(NEGF, NEGF, NEGF, NEGF);
        float4 sm = make_float4(0.f, 0.f, 0.f, 0.f);
        #pragma unroll 4
        for (int t = 0; t < tl; t++) {
            const uint2 u = *(const uint2*)(hbase + (size_t)s_idx[t] * DIM);
            const float2 f0 = __half22float2(*(const __half2*)&u.x);
            const float2 f1 = __half22float2(*(const __half2*)&u.y);
            mx.x = fmaxf(mx.x, f0.x); mx.y = fmaxf(mx.y, f0.y);
            mx.z = fmaxf(mx.z, f1.x); mx.w = fmaxf(mx.w, f1.y);
            sm.x += f0.x; sm.y += f0.y; sm.z += f1.x; sm.w += f1.y;
        }
        float4 av;
        if (tl > 0) {
            const float inv = 1.0f / (float)tl;
            av = make_float4(sm.x * inv, sm.y * inv, sm.z * inv, sm.w * inv);
        } else {
            mx = make_float4(0.f, 0.f, 0.f, 0.f);
            av = make_float4(0.f, 0.f, 0.f, 0.f);
        }
        *(float4*)(orow)           = mx;   // t_max
        *(float4*)(orow + 2 * DIM) = av;   // t_avg
    }

    // ---- desc pool ------------------------------------------------------------
    {
        float4 mx = make_float4(NEGF, NEGF, NEGF, NEGF);
        float4 sm = make_float4(0.f, 0.f, 0.f, 0.f);
        #pragma unroll 4
        for (int t = 0; t < dl; t++) {
            const uint2 u = *(const uint2*)(hbase + (size_t)s_idx[TT + t] * DIM);
            const float2 f0 = __half22float2(*(const __half2*)&u.x);
            const float2 f1 = __half22float2(*(const __half2*)&u.y);
            mx.x = fmaxf(mx.x, f0.x); mx.y = fmaxf(mx.y, f0.y);
            mx.z = fmaxf(mx.z, f1.x); mx.w = fmaxf(mx.w, f1.y);
            sm.x += f0.x; sm.y += f0.y; sm.z += f1.x; sm.w += f1.y;
        }
        float4 av;
        if (dl > 0) {
            const float inv = 1.0f / (float)dl;
            av = make_float4(sm.x * inv, sm.y * inv, sm.z * inv, sm.w * inv);
        } else {
            mx = make_float4(0.f, 0.f, 0.f, 0.f);
            av = make_float4(0.f, 0.f, 0.f, 0.f);
        }
        *(float4*)(orow + DIM)     = mx;   // d_max
        *(float4*)(orow + 3 * DIM) = av;   // d_avg
    }
}

extern "C" void kernel_launch(void* const* d_in, const int* in_sizes, int n_in,
                              void* d_out, int out_size)
{
    const void* title = d_in[0];
    const void* desc  = d_in[1];
    const void* tlen  = d_in[2];
    const void* dlen  = d_in[3];
    const float* w2v  = (const float*)d_in[n_in - 1];
    float* out        = (float*)d_out;

    const int B = in_sizes[2];                        // t_len has B elements

    // rows actually present in the table (clamped to scratch capacity)
    long long w2v_elems = in_sizes[n_in - 1];
    long long rows = w2v_elems / DIM;
    if (rows > MAX_ROWS) rows = MAX_ROWS;
    const int n4 = (int)(rows * (DIM / 4));           // float4 chunks

    __half* dsth;
    cudaGetSymbolAddress((void**)&dsth, g_w2v_h);     // no alloc, just address

    const int cgrid = (n4 + 255) / 256;
    w2v_convert_kernel<<<cgrid, 256>>>((const float4*)w2v, (uint2*)dsth, n4);
    swem_cat_kernel<<<B, 128>>>(title, desc, tlen, dlen, out);
}